// round 1
// baseline (speedup 1.0000x reference)
#include <cuda_runtime.h>
#include <cuda_bf16.h>
#include <cstdint>

#define NNODES 50000
#define DDIM   256
#define ETYPES 3
#define ET2    6
#define MEDGES 250000
#define KDIM   256

// ---------------- scratch (no cudaMalloc allowed) ----------------
__device__ float g_prop[(size_t)NNODES * 1536];   // h @ W^T + b  (N x ET2*D)
__device__ float g_msgs[(size_t)NNODES * DDIM];   // aggregated messages
__device__ float g_gi  [(size_t)NNODES * 768];    // msgs_scaled @ w_ih^T + b_ih
__device__ float g_gh  [(size_t)NNODES * 768];    // h @ w_hh^T + b_hh
__device__ float g_h1  [(size_t)NNODES * DDIM];   // h after timestep 0
__device__ float g_inv [NNODES];                  // 1 / divisor (doubles as counts buf)

// ---------------- degree / divisor ----------------
__global__ void count_kernel(const int* __restrict__ edges, float* __restrict__ cnt) {
    int g = blockIdx.x * blockDim.x + threadIdx.x;
    if (g >= ET2 * MEDGES) return;
    int i = g / MEDGES;
    int e = g - i * MEDGES;
    int t;
    if (i < ETYPES) {
        t = edges[((size_t)i * MEDGES + e) * 2 + 1];      // tgt = col 1
    } else {
        t = edges[((size_t)(i - ETYPES) * MEDGES + e) * 2 + 0]; // flipped: tgt = col 0
    }
    atomicAdd(&cnt[t], 1.0f);
}

__global__ void inv_kernel(float* __restrict__ cnt) {
    int v = blockIdx.x * blockDim.x + threadIdx.x;
    if (v >= NNODES) return;
    float c = cnt[v];
    float d = (c == 0.0f ? 1.0f : c) + 1e-8f;
    cnt[v] = 1.0f / d;
}

// ---------------- edge scatter: msgs[tgt] += prop[src, type, :] ----------------
// one warp per edge; 64 float4 per edge via red.global.add.v4.f32
__global__ void scatter_kernel(const float* __restrict__ prop,
                               const int* __restrict__ edges,
                               float* __restrict__ msgs) {
    int warp = (blockIdx.x * blockDim.x + threadIdx.x) >> 5;
    int lane = threadIdx.x & 31;
    if (warp >= ET2 * MEDGES) return;
    int i = warp / MEDGES;
    int e = warp - i * MEDGES;
    int s, t;
    if (i < ETYPES) {
        int2 p = ((const int2*)edges)[(size_t)i * MEDGES + e];
        s = p.x; t = p.y;
    } else {
        int2 p = ((const int2*)edges)[(size_t)(i - ETYPES) * MEDGES + e];
        s = p.y; t = p.x;
    }
    const float4* src = (const float4*)(prop + (size_t)s * 1536 + (size_t)i * DDIM);
    float4*       dst = (float4*)(msgs + (size_t)t * DDIM);
#pragma unroll
    for (int it = 0; it < 2; it++) {
        float4 v = src[lane + it * 32];
        float4* d = dst + lane + it * 32;
        asm volatile("red.global.add.v4.f32 [%0], {%1,%2,%3,%4};"
                     :: "l"(d), "f"(v.x), "f"(v.y), "f"(v.z), "f"(v.w)
                     : "memory");
    }
}

// ---------------- C = A @ B^T + bias, K = 256 ----------------
// A: Mrows x 256 (optionally row-scaled), B: Ncols x 256, C: Mrows x Ncols
// BM = BN = 128, BK = 8, 256 threads, 8x8 per thread
__global__ __launch_bounds__(256)
void sgemm_abT(const float* __restrict__ A, const float* __restrict__ B,
               const float* __restrict__ bias, const float* __restrict__ rowscale,
               float* __restrict__ C, int Mrows, int Ncols) {
    __shared__ float As[8][128];
    __shared__ float Bs[8][128];
    const int tid = threadIdx.x;
    const int tx = tid & 15;   // col group (8 cols)
    const int ty = tid >> 4;   // row group (8 rows)
    const int blockRow = blockIdx.y * 128;
    const int blockCol = blockIdx.x * 128;

    const int lr = tid >> 1;         // 0..127
    const int lk = (tid & 1) * 4;    // 0 or 4

    const int arow = blockRow + lr;
    const bool arow_ok = (arow < Mrows);
    float rs = 1.0f;
    if (rowscale != nullptr) rs = arow_ok ? rowscale[arow] : 0.0f;

    const float* Aptr = A + (size_t)(arow_ok ? arow : 0) * KDIM + lk;
    const float* Bptr = B + (size_t)(blockCol + lr) * KDIM + lk;

    float acc[8][8] = {};

    for (int kt = 0; kt < KDIM; kt += 8) {
        float4 a = arow_ok ? *(const float4*)(Aptr + kt) : make_float4(0.f, 0.f, 0.f, 0.f);
        float4 bv = *(const float4*)(Bptr + kt);
        if (rowscale != nullptr) { a.x *= rs; a.y *= rs; a.z *= rs; a.w *= rs; }
        As[lk + 0][lr] = a.x; As[lk + 1][lr] = a.y; As[lk + 2][lr] = a.z; As[lk + 3][lr] = a.w;
        Bs[lk + 0][lr] = bv.x; Bs[lk + 1][lr] = bv.y; Bs[lk + 2][lr] = bv.z; Bs[lk + 3][lr] = bv.w;
        __syncthreads();
#pragma unroll
        for (int kk = 0; kk < 8; kk++) {
            float ar[8], br[8];
#pragma unroll
            for (int i = 0; i < 8; i++) ar[i] = As[kk][ty * 8 + i];
#pragma unroll
            for (int j = 0; j < 8; j++) br[j] = Bs[kk][tx * 8 + j];
#pragma unroll
            for (int i = 0; i < 8; i++)
#pragma unroll
                for (int j = 0; j < 8; j++) acc[i][j] += ar[i] * br[j];
        }
        __syncthreads();
    }

#pragma unroll
    for (int i = 0; i < 8; i++) {
        int r = blockRow + ty * 8 + i;
        if (r >= Mrows) continue;
#pragma unroll
        for (int j = 0; j < 8; j += 4) {
            int c = blockCol + tx * 8 + j;
            float4 o;
            o.x = acc[i][j + 0] + bias[c + 0];
            o.y = acc[i][j + 1] + bias[c + 1];
            o.z = acc[i][j + 2] + bias[c + 2];
            o.w = acc[i][j + 3] + bias[c + 3];
            *(float4*)(C + (size_t)r * Ncols + c) = o;
        }
    }
}

// ---------------- GRU elementwise ----------------
__global__ void gru_kernel(const float* __restrict__ gi, const float* __restrict__ gh,
                           const float* __restrict__ h, float* __restrict__ out) {
    int idx = blockIdx.x * blockDim.x + threadIdx.x;
    if (idx >= NNODES * DDIM) return;
    int v = idx >> 8;          // / 256
    int j = idx & 255;
    size_t b = (size_t)v * 768;
    float ir = gi[b + j],        hr = gh[b + j];
    float iz = gi[b + 256 + j],  hz = gh[b + 256 + j];
    float in_ = gi[b + 512 + j], hn = gh[b + 512 + j];
    float r = 1.0f / (1.0f + expf(-(ir + hr)));
    float z = 1.0f / (1.0f + expf(-(iz + hz)));
    float n = tanhf(in_ + r * hn);
    out[idx] = (1.0f - z) * n + z * h[idx];
}

// ---------------- launch ----------------
extern "C" void kernel_launch(void* const* d_in, const int* in_sizes, int n_in,
                              void* d_out, int out_size) {
    const float* node_states = (const float*)d_in[0];
    const float* W           = (const float*)d_in[1];
    const float* b           = (const float*)d_in[2];
    const float* w_ih        = (const float*)d_in[3];
    const float* w_hh        = (const float*)d_in[4];
    const float* b_ih        = (const float*)d_in[5];
    const float* b_hh        = (const float*)d_in[6];
    const int*   edges       = (const int*)d_in[7];
    float* out = (float*)d_out;

    float *prop, *msgs, *gi, *gh, *h1, *inv;
    cudaGetSymbolAddress((void**)&prop, g_prop);
    cudaGetSymbolAddress((void**)&msgs, g_msgs);
    cudaGetSymbolAddress((void**)&gi,   g_gi);
    cudaGetSymbolAddress((void**)&gh,   g_gh);
    cudaGetSymbolAddress((void**)&h1,   g_h1);
    cudaGetSymbolAddress((void**)&inv,  g_inv);

    // degree -> inverse divisor (edge-only dependent; once per launch)
    cudaMemsetAsync(inv, 0, NNODES * sizeof(float), 0);
    count_kernel<<<(ET2 * MEDGES + 255) / 256, 256>>>(edges, inv);
    inv_kernel<<<(NNODES + 255) / 256, 256>>>(inv);

    const float* h = node_states;
    for (int t = 0; t < 2; t++) {
        cudaMemsetAsync(msgs, 0, (size_t)NNODES * DDIM * sizeof(float), 0);

        dim3 gProp(1536 / 128, (NNODES + 127) / 128);
        sgemm_abT<<<gProp, 256>>>(h, W, b, nullptr, prop, NNODES, 1536);

        scatter_kernel<<<(ET2 * MEDGES + 7) / 8, 256>>>(prop, edges, msgs);

        dim3 gGru(768 / 128, (NNODES + 127) / 128);
        sgemm_abT<<<gGru, 256>>>(msgs, w_ih, b_ih, inv, gi, NNODES, 768);
        sgemm_abT<<<gGru, 256>>>(h, w_hh, b_hh, nullptr, gh, NNODES, 768);

        float* hout = (t == 0) ? h1 : out;
        gru_kernel<<<(NNODES * DDIM + 255) / 256, 256>>>(gi, gh, h, hout);
        h = hout;
    }
}

// round 2
// speedup vs baseline: 2.0890x; 2.0890x over previous
#include <cuda_runtime.h>
#include <cuda_bf16.h>
#include <cstdint>

#define NNODES 50000
#define DDIM   256
#define ETYPES 3
#define ET2    6
#define MEDGES 250000
#define KDIM   256

#define BM 128
#define BN 128
#define BK 16
#define SROW 20          // smem row stride in floats (pad 16->20, 80B: 16B-aligned, conflict-free)
#define NKT (KDIM / BK)  // 16 k-tiles

// ---------------- scratch (no cudaMalloc allowed) ----------------
__device__ float g_prop[(size_t)NNODES * 1536];
__device__ float g_msgs[(size_t)NNODES * DDIM];
__device__ float g_gi  [(size_t)NNODES * 768];
__device__ float g_gh  [(size_t)NNODES * 768];
__device__ float g_h1  [(size_t)NNODES * DDIM];
__device__ float g_inv [NNODES];

// ---------------- degree / divisor ----------------
__global__ void count_kernel(const int* __restrict__ edges, float* __restrict__ cnt) {
    int g = blockIdx.x * blockDim.x + threadIdx.x;
    if (g >= ET2 * MEDGES) return;
    int i = g / MEDGES;
    int e = g - i * MEDGES;
    int t;
    if (i < ETYPES) t = edges[((size_t)i * MEDGES + e) * 2 + 1];
    else            t = edges[((size_t)(i - ETYPES) * MEDGES + e) * 2 + 0];
    atomicAdd(&cnt[t], 1.0f);
}

__global__ void inv_kernel(float* __restrict__ cnt) {
    int v = blockIdx.x * blockDim.x + threadIdx.x;
    if (v >= NNODES) return;
    float c = cnt[v];
    float d = (c == 0.0f ? 1.0f : c) + 1e-8f;
    cnt[v] = 1.0f / d;
}

// ---------------- edge scatter: msgs[tgt] += prop[src, type, :] ----------------
__global__ void scatter_kernel(const float* __restrict__ prop,
                               const int* __restrict__ edges,
                               float* __restrict__ msgs) {
    int warp = (blockIdx.x * blockDim.x + threadIdx.x) >> 5;
    int lane = threadIdx.x & 31;
    if (warp >= ET2 * MEDGES) return;
    int i = warp / MEDGES;
    int e = warp - i * MEDGES;
    int s, t;
    if (i < ETYPES) { int2 p = ((const int2*)edges)[(size_t)i * MEDGES + e]; s = p.x; t = p.y; }
    else            { int2 p = ((const int2*)edges)[(size_t)(i - ETYPES) * MEDGES + e]; s = p.y; t = p.x; }
    const float4* src = (const float4*)(prop + (size_t)s * 1536 + (size_t)i * DDIM);
    float4*       dst = (float4*)(msgs + (size_t)t * DDIM);
#pragma unroll
    for (int it = 0; it < 2; it++) {
        float4 v = src[lane + it * 32];
        float4* d = dst + lane + it * 32;
        asm volatile("red.global.add.v4.f32 [%0], {%1,%2,%3,%4};"
                     :: "l"(d), "f"(v.x), "f"(v.y), "f"(v.z), "f"(v.w)
                     : "memory");
    }
}

// ---------------- in-place row scale: msgs[v][:] *= inv[v] ----------------
__global__ void scale_kernel(float* __restrict__ msgs, const float* __restrict__ inv) {
    int idx = blockIdx.x * blockDim.x + threadIdx.x;        // float4 index
    if (idx >= NNODES * DDIM / 4) return;
    int v = idx >> 6;                                        // 64 float4 per row
    float s = inv[v];
    float4 x = ((float4*)msgs)[idx];
    x.x *= s; x.y *= s; x.z *= s; x.w *= s;
    ((float4*)msgs)[idx] = x;
}

// ---------------- TF32 tensor-core GEMM: C = A @ B^T + bias ----------------
__device__ __forceinline__ uint32_t f2tf32(float x) {
    uint32_t r; asm("cvt.rna.tf32.f32 %0, %1;" : "=r"(r) : "f"(x)); return r;
}

__device__ __forceinline__ void mma_tf32(float* c, const uint32_t* a, uint32_t b0, uint32_t b1) {
    asm volatile("mma.sync.aligned.m16n8k8.row.col.f32.tf32.tf32.f32 "
                 "{%0,%1,%2,%3}, {%4,%5,%6,%7}, {%8,%9}, {%0,%1,%2,%3};"
                 : "+f"(c[0]), "+f"(c[1]), "+f"(c[2]), "+f"(c[3])
                 : "r"(a[0]), "r"(a[1]), "r"(a[2]), "r"(a[3]), "r"(b0), "r"(b1));
}

#define CP_ASYNC16(dst, src, sz) \
    asm volatile("cp.async.ca.shared.global [%0], [%1], 16, %2;" \
                 :: "r"(dst), "l"(src), "r"(sz))

__global__ __launch_bounds__(256)
void tgemm_abT(const float* __restrict__ A, const float* __restrict__ B,
               const float* __restrict__ bias, float* __restrict__ C,
               int Mrows, int Ncols) {
    __shared__ float As[2][BM * SROW];
    __shared__ float Bs[2][BN * SROW];

    const int tid  = threadIdx.x;
    const int lane = tid & 31;
    const int warp = tid >> 5;
    const int wm   = warp >> 1;   // 0..3  (32-row slab)
    const int wn   = warp & 1;    // 0..1  (64-col slab)
    const int g    = lane >> 2;   // group id 0..7
    const int tg   = lane & 3;    // thread in group

    const int blockRow = blockIdx.y * BM;
    const int blockCol = blockIdx.x * BN;

    uint32_t as_base = (uint32_t)__cvta_generic_to_shared(&As[0][0]);
    uint32_t bs_base = (uint32_t)__cvta_generic_to_shared(&Bs[0][0]);
    const uint32_t BUFBYTES = BM * SROW * 4;

    // per-thread load slots: 2 x (row, c4) covering 128 rows x 4 float4-cols
    const int l_row0 = tid >> 2,          l_c4_0 = tid & 3;
    const int l_row1 = (tid + 256) >> 2,  l_c4_1 = (tid + 256) & 3;

    float acc[2][8][4];
#pragma unroll
    for (int mt = 0; mt < 2; mt++)
#pragma unroll
        for (int nt = 0; nt < 8; nt++)
#pragma unroll
            for (int q = 0; q < 4; q++) acc[mt][nt][q] = 0.0f;

    auto issue = [&](int kt, int buf) {
        // A tile: rows blockRow..+127, cols kt*16..+15
        {
            int grow = blockRow + l_row0;
            const float* src = A + (size_t)(grow < Mrows ? grow : Mrows - 1) * KDIM + kt * BK + l_c4_0 * 4;
            CP_ASYNC16(as_base + buf * BUFBYTES + (l_row0 * SROW + l_c4_0 * 4) * 4, src, grow < Mrows ? 16 : 0);
            grow = blockRow + l_row1;
            src = A + (size_t)(grow < Mrows ? grow : Mrows - 1) * KDIM + kt * BK + l_c4_1 * 4;
            CP_ASYNC16(as_base + buf * BUFBYTES + (l_row1 * SROW + l_c4_1 * 4) * 4, src, grow < Mrows ? 16 : 0);
        }
        // B tile: rows blockCol..+127 (always in range), cols kt*16..+15
        {
            const float* src = B + (size_t)(blockCol + l_row0) * KDIM + kt * BK + l_c4_0 * 4;
            CP_ASYNC16(bs_base + buf * BUFBYTES + (l_row0 * SROW + l_c4_0 * 4) * 4, src, 16);
            src = B + (size_t)(blockCol + l_row1) * KDIM + kt * BK + l_c4_1 * 4;
            CP_ASYNC16(bs_base + buf * BUFBYTES + (l_row1 * SROW + l_c4_1 * 4) * 4, src, 16);
        }
        asm volatile("cp.async.commit_group;");
    };

    issue(0, 0);
    int buf = 0;

    for (int kt = 0; kt < NKT; kt++) {
        if (kt + 1 < NKT) {
            issue(kt + 1, buf ^ 1);
            asm volatile("cp.async.wait_group 1;");
        } else {
            asm volatile("cp.async.wait_group 0;");
        }
        __syncthreads();

        const float* As_ = &As[buf][0];
        const float* Bs_ = &Bs[buf][0];

#pragma unroll
        for (int ks = 0; ks < 2; ks++) {
            const int k0 = ks * 8;
            uint32_t afrag[2][4];
#pragma unroll
            for (int mt = 0; mt < 2; mt++) {
                const float* base = As_ + (wm * 32 + mt * 16 + g) * SROW + k0 + tg;
                afrag[mt][0] = f2tf32(base[0]);
                afrag[mt][1] = f2tf32(base[8 * SROW]);
                afrag[mt][2] = f2tf32(base[4]);
                afrag[mt][3] = f2tf32(base[8 * SROW + 4]);
            }
#pragma unroll
            for (int nt = 0; nt < 8; nt++) {
                const float* bb = Bs_ + (wn * 64 + nt * 8 + g) * SROW + k0 + tg;
                uint32_t b0 = f2tf32(bb[0]);
                uint32_t b1 = f2tf32(bb[4]);
                mma_tf32(acc[0][nt], afrag[0], b0, b1);
                mma_tf32(acc[1][nt], afrag[1], b0, b1);
            }
        }
        __syncthreads();
        buf ^= 1;
    }

    // epilogue: C[r][c] = acc + bias[c]
#pragma unroll
    for (int mt = 0; mt < 2; mt++) {
        int r0 = blockRow + wm * 32 + mt * 16 + g;
#pragma unroll
        for (int nt = 0; nt < 8; nt++) {
            int c = blockCol + wn * 64 + nt * 8 + tg * 2;
            float bx = bias[c], by = bias[c + 1];
            if (r0 < Mrows) {
                float2 o = make_float2(acc[mt][nt][0] + bx, acc[mt][nt][1] + by);
                *(float2*)(C + (size_t)r0 * Ncols + c) = o;
            }
            if (r0 + 8 < Mrows) {
                float2 o = make_float2(acc[mt][nt][2] + bx, acc[mt][nt][3] + by);
                *(float2*)(C + (size_t)(r0 + 8) * Ncols + c) = o;
            }
        }
    }
}

// ---------------- GRU elementwise ----------------
__global__ void gru_kernel(const float* __restrict__ gi, const float* __restrict__ gh,
                           const float* __restrict__ h, float* __restrict__ out) {
    int idx = blockIdx.x * blockDim.x + threadIdx.x;
    if (idx >= NNODES * DDIM) return;
    int v = idx >> 8;
    int j = idx & 255;
    size_t b = (size_t)v * 768;
    float ir = gi[b + j],        hr = gh[b + j];
    float iz = gi[b + 256 + j],  hz = gh[b + 256 + j];
    float in_ = gi[b + 512 + j], hn = gh[b + 512 + j];
    float r = 1.0f / (1.0f + expf(-(ir + hr)));
    float z = 1.0f / (1.0f + expf(-(iz + hz)));
    float n = tanhf(in_ + r * hn);
    out[idx] = (1.0f - z) * n + z * h[idx];
}

// ---------------- launch ----------------
extern "C" void kernel_launch(void* const* d_in, const int* in_sizes, int n_in,
                              void* d_out, int out_size) {
    const float* node_states = (const float*)d_in[0];
    const float* W           = (const float*)d_in[1];
    const float* b           = (const float*)d_in[2];
    const float* w_ih        = (const float*)d_in[3];
    const float* w_hh        = (const float*)d_in[4];
    const float* b_ih        = (const float*)d_in[5];
    const float* b_hh        = (const float*)d_in[6];
    const int*   edges       = (const int*)d_in[7];
    float* out = (float*)d_out;

    float *prop, *msgs, *gi, *gh, *h1, *inv;
    cudaGetSymbolAddress((void**)&prop, g_prop);
    cudaGetSymbolAddress((void**)&msgs, g_msgs);
    cudaGetSymbolAddress((void**)&gi,   g_gi);
    cudaGetSymbolAddress((void**)&gh,   g_gh);
    cudaGetSymbolAddress((void**)&h1,   g_h1);
    cudaGetSymbolAddress((void**)&inv,  g_inv);

    cudaMemsetAsync(inv, 0, NNODES * sizeof(float), 0);
    count_kernel<<<(ET2 * MEDGES + 255) / 256, 256>>>(edges, inv);
    inv_kernel<<<(NNODES + 255) / 256, 256>>>(inv);

    const float* h = node_states;
    for (int t = 0; t < 2; t++) {
        cudaMemsetAsync(msgs, 0, (size_t)NNODES * DDIM * sizeof(float), 0);

        dim3 gProp(1536 / BN, (NNODES + BM - 1) / BM);
        tgemm_abT<<<gProp, 256>>>(h, W, b, prop, NNODES, 1536);

        scatter_kernel<<<(ET2 * MEDGES + 7) / 8, 256>>>(prop, edges, msgs);
        scale_kernel<<<(NNODES * DDIM / 4 + 255) / 256, 256>>>(msgs, inv);

        dim3 gGru(768 / BN, (NNODES + BM - 1) / BM);
        tgemm_abT<<<gGru, 256>>>(msgs, w_ih, b_ih, gi, NNODES, 768);
        tgemm_abT<<<gGru, 256>>>(h, w_hh, b_hh, gh, NNODES, 768);

        float* hout = (t == 0) ? h1 : out;
        gru_kernel<<<(NNODES * DDIM + 255) / 256, 256>>>(gi, gh, h, hout);
        h = hout;
    }
}

// round 3
// speedup vs baseline: 2.1941x; 1.0503x over previous
#include <cuda_runtime.h>
#include <cuda_bf16.h>
#include <cstdint>

#define NNODES 50000
#define DDIM   256
#define ETYPES 3
#define ET2    6
#define MEDGES 250000
#define KDIM   256

#define BM 256
#define BN 128
#define BK 16
#define SROW 20          // smem row stride in floats (80B: 16B-aligned, conflict-free)
#define NKT (KDIM / BK)  // 16 k-tiles
#define ABUF (BM * SROW) // floats per A buffer
#define BBUF (BN * SROW)
#define SMEM_BYTES ((2 * ABUF + 2 * BBUF) * 4)

// ---------------- scratch (no cudaMalloc allowed) ----------------
__device__ float g_prop[(size_t)NNODES * 1536];
__device__ float g_msgs[(size_t)NNODES * DDIM];
__device__ float g_gi  [(size_t)NNODES * 768];
__device__ float g_gh  [(size_t)NNODES * 768];
__device__ float g_h1  [(size_t)NNODES * DDIM];   // exact h after t=0
__device__ float g_hr  [(size_t)NNODES * DDIM];   // tf32-rounded h (GEMM A operand)
__device__ float g_inv [NNODES];
__device__ float g_Wr  [1536 * 256];
__device__ float g_wihr[768 * 256];
__device__ float g_whhr[768 * 256];

__device__ __forceinline__ float tf32r(float x) {
    uint32_t r; asm("cvt.rna.tf32.f32 %0, %1;" : "=r"(r) : "f"(x));
    return __uint_as_float(r);
}

// ---------------- tf32 pre-round pass ----------------
__global__ void round_kernel(const float* __restrict__ src, float* __restrict__ dst, int n4) {
    int i = blockIdx.x * blockDim.x + threadIdx.x;
    if (i >= n4) return;
    float4 x = ((const float4*)src)[i];
    x.x = tf32r(x.x); x.y = tf32r(x.y); x.z = tf32r(x.z); x.w = tf32r(x.w);
    ((float4*)dst)[i] = x;
}

// ---------------- degree / divisor ----------------
__global__ void count_kernel(const int* __restrict__ edges, float* __restrict__ cnt) {
    int g = blockIdx.x * blockDim.x + threadIdx.x;
    if (g >= ET2 * MEDGES) return;
    int i = g / MEDGES;
    int e = g - i * MEDGES;
    int t;
    if (i < ETYPES) t = edges[((size_t)i * MEDGES + e) * 2 + 1];
    else            t = edges[((size_t)(i - ETYPES) * MEDGES + e) * 2 + 0];
    atomicAdd(&cnt[t], 1.0f);
}

__global__ void inv_kernel(float* __restrict__ cnt) {
    int v = blockIdx.x * blockDim.x + threadIdx.x;
    if (v >= NNODES) return;
    float c = cnt[v];
    float d = (c == 0.0f ? 1.0f : c) + 1e-8f;
    cnt[v] = 1.0f / d;
}

// ---------------- edge scatter: msgs[tgt] += prop[src, type, :] ----------------
__global__ void scatter_kernel(const float* __restrict__ prop,
                               const int* __restrict__ edges,
                               float* __restrict__ msgs) {
    int warp = (blockIdx.x * blockDim.x + threadIdx.x) >> 5;
    int lane = threadIdx.x & 31;
    if (warp >= ET2 * MEDGES) return;
    int i = warp / MEDGES;
    int e = warp - i * MEDGES;
    int s, t;
    if (i < ETYPES) { int2 p = ((const int2*)edges)[(size_t)i * MEDGES + e]; s = p.x; t = p.y; }
    else            { int2 p = ((const int2*)edges)[(size_t)(i - ETYPES) * MEDGES + e]; s = p.y; t = p.x; }
    const float4* src = (const float4*)(prop + (size_t)s * 1536 + (size_t)i * DDIM);
    float4*       dst = (float4*)(msgs + (size_t)t * DDIM);
#pragma unroll
    for (int it = 0; it < 2; it++) {
        float4 v = __ldcs(src + lane + it * 32);   // evict-first: don't pollute L2
        float4* d = dst + lane + it * 32;
        asm volatile("red.global.add.v4.f32 [%0], {%1,%2,%3,%4};"
                     :: "l"(d), "f"(v.x), "f"(v.y), "f"(v.z), "f"(v.w)
                     : "memory");
    }
}

// ---------------- in-place row scale + tf32 round ----------------
__global__ void scale_round_kernel(float* __restrict__ msgs, const float* __restrict__ inv) {
    int idx = blockIdx.x * blockDim.x + threadIdx.x;
    if (idx >= NNODES * DDIM / 4) return;
    int v = idx >> 6;
    float s = inv[v];
    float4 x = ((float4*)msgs)[idx];
    x.x = tf32r(x.x * s); x.y = tf32r(x.y * s); x.z = tf32r(x.z * s); x.w = tf32r(x.w * s);
    ((float4*)msgs)[idx] = x;
}

// ---------------- TF32 tensor-core GEMM: C = A @ B^T + bias ----------------
// A, B already tf32-rounded. CTA tile 256x128, warp tile 64x64, BK=16.
__device__ __forceinline__ void mma_tf32(float* c, const uint32_t* a, uint32_t b0, uint32_t b1) {
    asm volatile("mma.sync.aligned.m16n8k8.row.col.f32.tf32.tf32.f32 "
                 "{%0,%1,%2,%3}, {%4,%5,%6,%7}, {%8,%9}, {%0,%1,%2,%3};"
                 : "+f"(c[0]), "+f"(c[1]), "+f"(c[2]), "+f"(c[3])
                 : "r"(a[0]), "r"(a[1]), "r"(a[2]), "r"(a[3]), "r"(b0), "r"(b1));
}

#define CP_ASYNC16(dst, src, sz) \
    asm volatile("cp.async.ca.shared.global [%0], [%1], 16, %2;" \
                 :: "r"(dst), "l"(src), "r"(sz))

__global__ __launch_bounds__(256, 1)
void tgemm_abT(const float* __restrict__ A, const float* __restrict__ B,
               const float* __restrict__ bias, float* __restrict__ C,
               int Mrows, int Ncols) {
    extern __shared__ float smem[];
    float* Asm = smem;                 // [2][ABUF]
    float* Bsm = smem + 2 * ABUF;      // [2][BBUF]

    const int tid  = threadIdx.x;
    const int lane = tid & 31;
    const int warp = tid >> 5;
    const int wm   = warp >> 1;   // 0..3: 64-row slab
    const int wn   = warp & 1;    // 0..1: 64-col slab
    const int g    = lane >> 2;
    const int tg   = lane & 3;

    const int blockRow = blockIdx.y * BM;
    const int blockCol = blockIdx.x * BN;

    uint32_t as_base = (uint32_t)__cvta_generic_to_shared(Asm);
    uint32_t bs_base = (uint32_t)__cvta_generic_to_shared(Bsm);

    const int l_c4 = tid & 3;
    const int l_r0 = tid >> 2;   // 0..63

    float acc[4][8][4];
#pragma unroll
    for (int mt = 0; mt < 4; mt++)
#pragma unroll
        for (int nt = 0; nt < 8; nt++)
#pragma unroll
            for (int q = 0; q < 4; q++) acc[mt][nt][q] = 0.0f;

    auto issue = [&](int kt, int buf) {
#pragma unroll
        for (int j = 0; j < 4; j++) {
            int row = l_r0 + 64 * j;
            int grow = blockRow + row;
            const float* src = A + (size_t)(grow < Mrows ? grow : Mrows - 1) * KDIM + kt * BK + l_c4 * 4;
            CP_ASYNC16(as_base + (buf * ABUF + row * SROW + l_c4 * 4) * 4, src, grow < Mrows ? 16 : 0);
        }
#pragma unroll
        for (int j = 0; j < 2; j++) {
            int row = l_r0 + 64 * j;
            const float* src = B + (size_t)(blockCol + row) * KDIM + kt * BK + l_c4 * 4;
            CP_ASYNC16(bs_base + (buf * BBUF + row * SROW + l_c4 * 4) * 4, src, 16);
        }
        asm volatile("cp.async.commit_group;");
    };

    issue(0, 0);
    int buf = 0;

    for (int kt = 0; kt < NKT; kt++) {
        if (kt + 1 < NKT) {
            issue(kt + 1, buf ^ 1);
            asm volatile("cp.async.wait_group 1;");
        } else {
            asm volatile("cp.async.wait_group 0;");
        }
        __syncthreads();

        const float* As_ = Asm + buf * ABUF;
        const float* Bs_ = Bsm + buf * BBUF;

#pragma unroll
        for (int ks = 0; ks < 2; ks++) {
            const int k0 = ks * 8;
            uint32_t af[4][4];
#pragma unroll
            for (int mt = 0; mt < 4; mt++) {
                const float* base = As_ + (wm * 64 + mt * 16 + g) * SROW + k0 + tg;
                af[mt][0] = __float_as_uint(base[0]);
                af[mt][1] = __float_as_uint(base[8 * SROW]);
                af[mt][2] = __float_as_uint(base[4]);
                af[mt][3] = __float_as_uint(base[8 * SROW + 4]);
            }
#pragma unroll
            for (int nt = 0; nt < 8; nt++) {
                const float* bb = Bs_ + (wn * 64 + nt * 8 + g) * SROW + k0 + tg;
                uint32_t b0 = __float_as_uint(bb[0]);
                uint32_t b1 = __float_as_uint(bb[4]);
#pragma unroll
                for (int mt = 0; mt < 4; mt++)
                    mma_tf32(acc[mt][nt], af[mt], b0, b1);
            }
        }
        __syncthreads();
        buf ^= 1;
    }

#pragma unroll
    for (int mt = 0; mt < 4; mt++) {
        int r0 = blockRow + wm * 64 + mt * 16 + g;
#pragma unroll
        for (int nt = 0; nt < 8; nt++) {
            int c = blockCol + wn * 64 + nt * 8 + tg * 2;
            float bx = bias[c], by = bias[c + 1];
            if (r0 < Mrows) {
                float2 o = make_float2(acc[mt][nt][0] + bx, acc[mt][nt][1] + by);
                *(float2*)(C + (size_t)r0 * Ncols + c) = o;
            }
            if (r0 + 8 < Mrows) {
                float2 o = make_float2(acc[mt][nt][2] + bx, acc[mt][nt][3] + by);
                *(float2*)(C + (size_t)(r0 + 8) * Ncols + c) = o;
            }
        }
    }
}

// ---------------- GRU elementwise (+ optional rounded-h side output) ----------------
__global__ void gru_kernel(const float* __restrict__ gi, const float* __restrict__ gh,
                           const float* __restrict__ h, float* __restrict__ out,
                           float* __restrict__ hr) {
    int idx = blockIdx.x * blockDim.x + threadIdx.x;
    if (idx >= NNODES * DDIM) return;
    int v = idx >> 8;
    int j = idx & 255;
    size_t b = (size_t)v * 768;
    float ir = gi[b + j],        hr_ = gh[b + j];
    float iz = gi[b + 256 + j],  hz  = gh[b + 256 + j];
    float in_ = gi[b + 512 + j], hn  = gh[b + 512 + j];
    float r = 1.0f / (1.0f + expf(-(ir + hr_)));
    float z = 1.0f / (1.0f + expf(-(iz + hz)));
    float n = tanhf(in_ + r * hn);
    float o = (1.0f - z) * n + z * h[idx];
    out[idx] = o;
    if (hr != nullptr) hr[idx] = tf32r(o);
}

// ---------------- launch ----------------
extern "C" void kernel_launch(void* const* d_in, const int* in_sizes, int n_in,
                              void* d_out, int out_size) {
    const float* node_states = (const float*)d_in[0];
    const float* W           = (const float*)d_in[1];
    const float* b           = (const float*)d_in[2];
    const float* w_ih        = (const float*)d_in[3];
    const float* w_hh        = (const float*)d_in[4];
    const float* b_ih        = (const float*)d_in[5];
    const float* b_hh        = (const float*)d_in[6];
    const int*   edges       = (const int*)d_in[7];
    float* out = (float*)d_out;

    float *prop, *msgs, *gi, *gh, *h1, *hr, *inv, *Wr, *wihr, *whhr;
    cudaGetSymbolAddress((void**)&prop, g_prop);
    cudaGetSymbolAddress((void**)&msgs, g_msgs);
    cudaGetSymbolAddress((void**)&gi,   g_gi);
    cudaGetSymbolAddress((void**)&gh,   g_gh);
    cudaGetSymbolAddress((void**)&h1,   g_h1);
    cudaGetSymbolAddress((void**)&hr,   g_hr);
    cudaGetSymbolAddress((void**)&inv,  g_inv);
    cudaGetSymbolAddress((void**)&Wr,   g_Wr);
    cudaGetSymbolAddress((void**)&wihr, g_wihr);
    cudaGetSymbolAddress((void**)&whhr, g_whhr);

    cudaFuncSetAttribute(tgemm_abT, cudaFuncAttributeMaxDynamicSharedMemorySize, SMEM_BYTES);

    // one-time per launch: round weights + h0, degree/divisor
    round_kernel<<<(1536 * 256 / 4 + 255) / 256, 256>>>(W, Wr, 1536 * 256 / 4);
    round_kernel<<<(768 * 256 / 4 + 255) / 256, 256>>>(w_ih, wihr, 768 * 256 / 4);
    round_kernel<<<(768 * 256 / 4 + 255) / 256, 256>>>(w_hh, whhr, 768 * 256 / 4);
    round_kernel<<<(NNODES * DDIM / 4 + 255) / 256, 256>>>(node_states, hr, NNODES * DDIM / 4);

    cudaMemsetAsync(inv, 0, NNODES * sizeof(float), 0);
    count_kernel<<<(ET2 * MEDGES + 255) / 256, 256>>>(edges, inv);
    inv_kernel<<<(NNODES + 255) / 256, 256>>>(inv);

    const float* h = node_states;   // exact h for GRU
    for (int t = 0; t < 2; t++) {
        cudaMemsetAsync(msgs, 0, (size_t)NNODES * DDIM * sizeof(float), 0);

        dim3 gProp(1536 / BN, (NNODES + BM - 1) / BM);
        tgemm_abT<<<gProp, 256, SMEM_BYTES>>>(hr, Wr, b, prop, NNODES, 1536);

        scatter_kernel<<<(ET2 * MEDGES + 7) / 8, 256>>>(prop, edges, msgs);
        scale_round_kernel<<<(NNODES * DDIM / 4 + 255) / 256, 256>>>(msgs, inv);

        dim3 gGru(768 / BN, (NNODES + BM - 1) / BM);
        tgemm_abT<<<gGru, 256, SMEM_BYTES>>>(msgs, wihr, b_ih, gi, NNODES, 768);
        tgemm_abT<<<gGru, 256, SMEM_BYTES>>>(hr, whhr, b_hh, gh, NNODES, 768);

        float* hout = (t == 0) ? h1 : out;
        gru_kernel<<<(NNODES * DDIM + 255) / 256, 256>>>(gi, gh, h, hout,
                                                         (t == 0) ? hr : nullptr);
        h = hout;
    }
}

// round 5
// speedup vs baseline: 3.0498x; 1.3900x over previous
#include <cuda_runtime.h>
#include <cuda_fp16.h>
#include <cstdint>

#define NNODES 50000
#define DDIM   256
#define ETYPES 3
#define ET2    6
#define MEDGES 250000
#define KDIM   256

// ---------------- fp16 HMMA GEMM config ----------------
#define GBM 128
#define GBN 128
#define GBK 32            // halves per k-tile (64B per row)
#define GSTR 80           // smem row stride in bytes (64B data + 16B pad)
#define GBUF (128 * GSTR) // 10240 B per tile buffer
#define GNKT (KDIM / GBK) // 8 k-tiles

// ---------------- scratch (no cudaMalloc allowed) ----------------
__device__ float  g_prop [(size_t)NNODES * 1536];
__device__ float  g_msgs [(size_t)NNODES * DDIM];
__device__ __half g_msgsh[(size_t)NNODES * DDIM];
__device__ float  g_gi   [(size_t)NNODES * 768];
__device__ float  g_gh   [(size_t)NNODES * 768];
__device__ float  g_h1   [(size_t)NNODES * DDIM];  // exact h after t=0
__device__ __half g_hh   [(size_t)NNODES * DDIM];  // fp16 h (GEMM A operand)
__device__ float  g_inv  [NNODES];
__device__ __half g_Wh   [1536 * 256];
__device__ __half g_wihh [768 * 256];
__device__ __half g_whhh [768 * 256];

// ---------------- small kernels ----------------
__global__ void tohalf_kernel(const float* __restrict__ src, __half* __restrict__ dst, int n4) {
    int i = blockIdx.x * blockDim.x + threadIdx.x;
    if (i >= n4) return;
    float4 x = ((const float4*)src)[i];
    __half2* d = (__half2*)dst;
    d[2 * i]     = __floats2half2_rn(x.x, x.y);
    d[2 * i + 1] = __floats2half2_rn(x.z, x.w);
}

__global__ void count_kernel(const int* __restrict__ edges, float* __restrict__ cnt) {
    int g = blockIdx.x * blockDim.x + threadIdx.x;
    if (g >= ET2 * MEDGES) return;
    int i = g / MEDGES;
    int e = g - i * MEDGES;
    int t;
    if (i < ETYPES) t = edges[((size_t)i * MEDGES + e) * 2 + 1];
    else            t = edges[((size_t)(i - ETYPES) * MEDGES + e) * 2 + 0];
    atomicAdd(&cnt[t], 1.0f);
}

__global__ void inv_kernel(float* __restrict__ cnt) {
    int v = blockIdx.x * blockDim.x + threadIdx.x;
    if (v >= NNODES) return;
    float c = cnt[v];
    float d = (c == 0.0f ? 1.0f : c) + 1e-8f;
    cnt[v] = 1.0f / d;
}

__global__ void scatter_kernel(const float* __restrict__ prop,
                               const int* __restrict__ edges,
                               float* __restrict__ msgs) {
    int warp = (blockIdx.x * blockDim.x + threadIdx.x) >> 5;
    int lane = threadIdx.x & 31;
    if (warp >= ET2 * MEDGES) return;
    int i = warp / MEDGES;
    int e = warp - i * MEDGES;
    int s, t;
    if (i < ETYPES) { int2 p = ((const int2*)edges)[(size_t)i * MEDGES + e]; s = p.x; t = p.y; }
    else            { int2 p = ((const int2*)edges)[(size_t)(i - ETYPES) * MEDGES + e]; s = p.y; t = p.x; }
    const float4* src = (const float4*)(prop + (size_t)s * 1536 + (size_t)i * DDIM);
    float4*       dst = (float4*)(msgs + (size_t)t * DDIM);
#pragma unroll
    for (int it = 0; it < 2; it++) {
        float4 v = __ldcs(src + lane + it * 32);
        float4* d = dst + lane + it * 32;
        asm volatile("red.global.add.v4.f32 [%0], {%1,%2,%3,%4};"
                     :: "l"(d), "f"(v.x), "f"(v.y), "f"(v.z), "f"(v.w)
                     : "memory");
    }
}

// scale by 1/deg and convert to half in one pass
__global__ void scale_half_kernel(const float* __restrict__ msgs,
                                  const float* __restrict__ inv,
                                  __half* __restrict__ msgsh) {
    int idx = blockIdx.x * blockDim.x + threadIdx.x;
    if (idx >= NNODES * DDIM / 4) return;
    int v = idx >> 6;
    float s = inv[v];
    float4 x = ((const float4*)msgs)[idx];
    __half2* d = (__half2*)msgsh;
    d[2 * idx]     = __floats2half2_rn(x.x * s, x.y * s);
    d[2 * idx + 1] = __floats2half2_rn(x.z * s, x.w * s);
}

// ---------------- fp16 tensor-core GEMM: C = A @ B^T + bias ----------------
// A: [Mrows, 256] half, B: [Ncols, 256] half, C: [Mrows, Ncols] fp32
__device__ __forceinline__ void mma_f16(float* c, const uint32_t* a, uint32_t b0, uint32_t b1) {
    asm volatile("mma.sync.aligned.m16n8k16.row.col.f32.f16.f16.f32 "
                 "{%0,%1,%2,%3}, {%4,%5,%6,%7}, {%8,%9}, {%0,%1,%2,%3};"
                 : "+f"(c[0]), "+f"(c[1]), "+f"(c[2]), "+f"(c[3])
                 : "r"(a[0]), "r"(a[1]), "r"(a[2]), "r"(a[3]), "r"(b0), "r"(b1));
}

#define LDSM_X4(r, addr)                                                        \
    asm volatile("ldmatrix.sync.aligned.m8n8.x4.shared.b16 {%0,%1,%2,%3}, [%4];" \
                 : "=r"((r)[0]), "=r"((r)[1]), "=r"((r)[2]), "=r"((r)[3])       \
                 : "r"(addr))

#define CP_ASYNC16(dst, src) \
    asm volatile("cp.async.cg.shared.global [%0], [%1], 16;" :: "r"(dst), "l"(src))

__global__ __launch_bounds__(256, 2)
void hgemm_abT(const __half* __restrict__ A, const __half* __restrict__ B,
               const float* __restrict__ bias, float* __restrict__ C,
               int Mrows, int Ncols) {
    __shared__ __align__(16) char smem[4 * GBUF];   // As[2], Bs[2]
    const uint32_t as_base = (uint32_t)__cvta_generic_to_shared(smem);
    const uint32_t bs_base = as_base + 2 * GBUF;

    const int tid  = threadIdx.x;
    const int lane = tid & 31;
    const int warp = tid >> 5;
    const int wm   = warp & 1;    // 2 m-slabs of 64
    const int wn   = warp >> 1;   // 4 n-slabs of 32

    const int blockRow = blockIdx.y * GBM;
    const int blockCol = blockIdx.x * GBN;

    const int l_row = tid >> 1;            // 0..127
    const int l_c2  = (tid & 1) * 2;       // chunk pair: 0 or 2

    float acc[4][4][4];
#pragma unroll
    for (int mt = 0; mt < 4; mt++)
#pragma unroll
        for (int nt = 0; nt < 4; nt++)
#pragma unroll
            for (int q = 0; q < 4; q++) acc[mt][nt][q] = 0.0f;

    auto issue = [&](int kt, int buf) {
        // A: 128 rows x 4 chunks(16B); thread -> row=tid>>1, chunks {l_c2, l_c2+1} (32B contiguous)
        {
            int grow = blockRow + l_row; if (grow >= Mrows) grow = Mrows - 1;
            const __half* src = A + (size_t)grow * KDIM + kt * GBK + l_c2 * 8;
            uint32_t dst = as_base + buf * GBUF + l_row * GSTR + l_c2 * 16;
            CP_ASYNC16(dst, src);
            CP_ASYNC16(dst + 16, src + 8);
        }
        {
            const __half* src = B + (size_t)(blockCol + l_row) * KDIM + kt * GBK + l_c2 * 8;
            uint32_t dst = bs_base + buf * GBUF + l_row * GSTR + l_c2 * 16;
            CP_ASYNC16(dst, src);
            CP_ASYNC16(dst + 16, src + 8);
        }
        asm volatile("cp.async.commit_group;");
    };

    issue(0, 0);
    issue(1, 1);
    int buf = 0;

    for (int kt = 0; kt < GNKT; kt++) {
        if (kt + 2 < GNKT) asm volatile("cp.async.wait_group 1;");
        else if (kt + 1 < GNKT) asm volatile("cp.async.wait_group 1;");
        else asm volatile("cp.async.wait_group 0;");
        __syncthreads();

        const uint32_t as = as_base + buf * GBUF;
        const uint32_t bs = bs_base + buf * GBUF;

#pragma unroll
        for (int ks = 0; ks < 2; ks++) {
            uint32_t af[4][4];
#pragma unroll
            for (int mt = 0; mt < 4; mt++) {
                int row = wm * 64 + mt * 16 + (lane & 15);
                uint32_t addr = as + row * GSTR + (ks * 2 + (lane >> 4)) * 16;
                LDSM_X4(af[mt], addr);
            }
            uint32_t bf[2][4];
#pragma unroll
            for (int bt = 0; bt < 2; bt++) {
                int nrow = wn * 32 + bt * 16 + (lane & 7) + ((lane >> 4) << 3);
                uint32_t addr = bs + nrow * GSTR + (ks * 2 + ((lane >> 3) & 1)) * 16;
                LDSM_X4(bf[bt], addr);
            }
#pragma unroll
            for (int mt = 0; mt < 4; mt++)
#pragma unroll
                for (int nt = 0; nt < 4; nt++)
                    mma_f16(acc[mt][nt], af[mt],
                            bf[nt >> 1][(nt & 1) * 2], bf[nt >> 1][(nt & 1) * 2 + 1]);
        }
        __syncthreads();
        buf ^= 1;
        if (kt + 2 < GNKT) issue(kt + 2, buf ^ 1);
    }

    // epilogue: C[r][c] = acc + bias[c]
#pragma unroll
    for (int mt = 0; mt < 4; mt++) {
        int r0 = blockRow + wm * 64 + mt * 16 + (lane >> 2);
#pragma unroll
        for (int nt = 0; nt < 4; nt++) {
            int c = blockCol + wn * 32 + nt * 8 + 2 * (lane & 3);
            float bx = bias[c], by = bias[c + 1];
            if (r0 < Mrows) {
                float2 o = make_float2(acc[mt][nt][0] + bx, acc[mt][nt][1] + by);
                *(float2*)(C + (size_t)r0 * Ncols + c) = o;
            }
            if (r0 + 8 < Mrows) {
                float2 o = make_float2(acc[mt][nt][2] + bx, acc[mt][nt][3] + by);
                *(float2*)(C + (size_t)(r0 + 8) * Ncols + c) = o;
            }
        }
    }
}

// ---------------- GRU elementwise (+ fp16 side output of new h) ----------------
__global__ void gru_kernel(const float* __restrict__ gi, const float* __restrict__ gh,
                           const float* __restrict__ h, float* __restrict__ out,
                           __half* __restrict__ hh) {
    int idx = blockIdx.x * blockDim.x + threadIdx.x;
    if (idx >= NNODES * DDIM) return;
    int v = idx >> 8;
    int j = idx & 255;
    size_t b = (size_t)v * 768;
    float ir = gi[b + j],        hr_ = gh[b + j];
    float iz = gi[b + 256 + j],  hz  = gh[b + 256 + j];
    float in_ = gi[b + 512 + j], hn  = gh[b + 512 + j];
    float r = 1.0f / (1.0f + expf(-(ir + hr_)));
    float z = 1.0f / (1.0f + expf(-(iz + hz)));
    float n = tanhf(in_ + r * hn);
    float o = (1.0f - z) * n + z * h[idx];
    out[idx] = o;
    if (hh != nullptr) hh[idx] = __float2half_rn(o);
}

// ---------------- launch ----------------
extern "C" void kernel_launch(void* const* d_in, const int* in_sizes, int n_in,
                              void* d_out, int out_size) {
    const float* node_states = (const float*)d_in[0];
    const float* W           = (const float*)d_in[1];
    const float* b           = (const float*)d_in[2];
    const float* w_ih        = (const float*)d_in[3];
    const float* w_hh        = (const float*)d_in[4];
    const float* b_ih        = (const float*)d_in[5];
    const float* b_hh        = (const float*)d_in[6];
    const int*   edges       = (const int*)d_in[7];
    float* out = (float*)d_out;

    float *prop, *msgs, *gi, *gh, *h1, *inv;
    __half *msgsh, *hh, *Wh, *wihh, *whhh;
    cudaGetSymbolAddress((void**)&prop,  g_prop);
    cudaGetSymbolAddress((void**)&msgs,  g_msgs);
    cudaGetSymbolAddress((void**)&msgsh, g_msgsh);
    cudaGetSymbolAddress((void**)&gi,    g_gi);
    cudaGetSymbolAddress((void**)&gh,    g_gh);
    cudaGetSymbolAddress((void**)&h1,    g_h1);
    cudaGetSymbolAddress((void**)&hh,    g_hh);
    cudaGetSymbolAddress((void**)&inv,   g_inv);
    cudaGetSymbolAddress((void**)&Wh,    g_Wh);
    cudaGetSymbolAddress((void**)&wihh,  g_wihh);
    cudaGetSymbolAddress((void**)&whhh,  g_whhh);

    tohalf_kernel<<<(1536 * 256 / 4 + 255) / 256, 256>>>(W, Wh, 1536 * 256 / 4);
    tohalf_kernel<<<(768 * 256 / 4 + 255) / 256, 256>>>(w_ih, wihh, 768 * 256 / 4);
    tohalf_kernel<<<(768 * 256 / 4 + 255) / 256, 256>>>(w_hh, whhh, 768 * 256 / 4);
    tohalf_kernel<<<(NNODES * DDIM / 4 + 255) / 256, 256>>>(node_states, hh, NNODES * DDIM / 4);

    cudaMemsetAsync(inv, 0, NNODES * sizeof(float), 0);
    count_kernel<<<(ET2 * MEDGES + 255) / 256, 256>>>(edges, inv);
    inv_kernel<<<(NNODES + 255) / 256, 256>>>(inv);

    const int MT = (NNODES + GBM - 1) / GBM;   // 391
    const float* h = node_states;
    for (int t = 0; t < 2; t++) {
        cudaMemsetAsync(msgs, 0, (size_t)NNODES * DDIM * sizeof(float), 0);

        hgemm_abT<<<dim3(1536 / GBN, MT), 256>>>(hh, Wh, b, prop, NNODES, 1536);

        scatter_kernel<<<(ET2 * MEDGES + 7) / 8, 256>>>(prop, edges, msgs);
        scale_half_kernel<<<(NNODES * DDIM / 4 + 255) / 256, 256>>>(msgs, inv, msgsh);

        hgemm_abT<<<dim3(768 / GBN, MT), 256>>>(msgsh, wihh, b_ih, gi, NNODES, 768);
        hgemm_abT<<<dim3(768 / GBN, MT), 256>>>(hh, whhh, b_hh, gh, NNODES, 768);

        float* hout = (t == 0) ? h1 : out;
        gru_kernel<<<(NNODES * DDIM + 255) / 256, 256>>>(gi, gh, h, hout,
                                                         (t == 0) ? hh : nullptr);
        h = hout;
    }
}